// round 10
// baseline (speedup 1.0000x reference)
#include <cuda_runtime.h>
#include <cuda_fp16.h>
#include <cstdint>

// Dendrite: out[b,d] = sum_{v=1..255} lin_w[v-1] * prod_{s: bit(7-s) of v} p_s + lin_b,
//   p_s = sigmoid(k*(w*x-q)).
// Multilinear Horner with V-PAIRED half2 lanes: coefficient half2 holds
// (c[hi_even*16+lo], c[hi_odd*16+lo]); one HFMA2 advances the inner Horner
// tree for BOTH hi-parities of one batch row. Lane combine (lo + p3*hi) IS
// the first outer Horner level. T=1 row/thread -> 8192 warps (max supply).
// Outer levels in fp32.

static constexpr int B = 8192;
static constexpr int D = 32;
static constexpr int S = 8;

__device__ __forceinline__ float fast_sigmoid_prehalved(float arg_half) {
    // sigmoid(a) = 0.5*tanh(a/2)+0.5 ; caller supplies a/2.
    float t;
    asm("tanh.approx.f32 %0, %1;" : "=f"(t) : "f"(arg_half));
    return fmaf(0.5f, t, 0.5f);
}

struct __align__(16) H2x4 { __half2 a, b, c, d; };

__global__ __launch_bounds__(128)
void dendrite_kernel(const float* __restrict__ x,      // [B, 1, S]
                     const float* __restrict__ k,      // [D, S]
                     const float* __restrict__ w,      // [D, S]
                     const float* __restrict__ q,      // [D, S]
                     const float* __restrict__ lin_w,  // [1, 255]
                     const float* __restrict__ lin_b,  // [1]
                     float* __restrict__ out)          // [B, 1, D] -> b*D + d
{
    // sW2[t*16+lo] = ( c[(2t)*16+lo] , c[(2t+1)*16+lo] ), t=0..7, lo=0..15
    __shared__ __align__(16) __half2 sW2[128];   // 512 B
    __shared__ float sA[S][D];                   // [s][d] = 0.5*k*w
    __shared__ float sC[S][D];                   // [s][d] = -0.5*k*q

    const int tid = threadIdx.x;   // 128 threads
    {
        // coefficient table (128 entries, one per thread)
        const int t = tid >> 4, lo = tid & 15;
        const int vE = t * 32 + lo;        // hi = 2t
        const int vO = vE + 16;            // hi = 2t+1
        const float cE = (vE == 0) ? 0.0f : lin_w[vE - 1];
        const float cO = lin_w[vO - 1];    // vO >= 16, never the empty subset
        sW2[tid] = __floats2half2_rn(cE, cO);

        // gate params (256 entries, two per thread)
#pragma unroll
        for (int i = tid; i < 256; i += 128) {
            const int dd = i >> 3, ss = i & 7;   // i = d*8 + s matches flat [D,S]
            const float kh = 0.5f * k[i];
            sA[ss][dd] = kh * w[i];
            sC[ss][dd] = -kh * q[i];
        }
    }
    __syncthreads();

    const int d = tid & 31;                 // lane = d
    const int warp = tid >> 5;              // 4 warps/block, 1 row each
    const int b = blockIdx.x * 4 + warp;

    // x row (uniform across warp -> broadcast LDG.128)
    const float4* xp = reinterpret_cast<const float4*>(x + b * S);
    const float4 xa = xp[0], xb = xp[1];
    const float xs[8] = {xa.x, xa.y, xa.z, xa.w, xb.x, xb.y, xb.z, xb.w};

    // Sigmoids: p0..p3 stay fp32 (outer levels); p4..p7 duplicated into half2
    // lanes (inner-tree multipliers, same value both lanes).
    float Pf[4];
    __half2 p4h, p5h, p6h, p7h;
#pragma unroll
    for (int s = 0; s < 8; ++s) {
        const float p = fast_sigmoid_prehalved(fmaf(sA[s][d], xs[s], sC[s][d]));
        if (s < 4) Pf[s] = p;
        else {
            const __half2 ph = __half2half2(__float2half_rn(p));
            if (s == 4) p4h = ph; else if (s == 5) p5h = ph;
            else if (s == 6) p6h = ph; else p7h = ph;
        }
    }

    // 8 t-blocks; each: 4 LDS.128 + 15 HFMA2 -> packed (inner_even, inner_odd),
    // then lane-combine u[t] = even + p3*odd (first outer level, fp32).
    float u[8];
    const H2x4* W4 = reinterpret_cast<const H2x4*>(sW2);
#pragma unroll
    for (int t = 0; t < 8; ++t) {
        const H2x4 q0 = W4[t * 4 + 0];   // lo = 0..3
        const H2x4 q1 = W4[t * 4 + 1];   // lo = 4..7
        const H2x4 q2 = W4[t * 4 + 2];   // lo = 8..11
        const H2x4 q3 = W4[t * 4 + 3];   // lo = 12..15

        // level A (p7): 8 hfma2
        const __half2 e0 = __hfma2(p7h, q0.b, q0.a);
        const __half2 e1 = __hfma2(p7h, q0.d, q0.c);
        const __half2 e2 = __hfma2(p7h, q1.b, q1.a);
        const __half2 e3 = __hfma2(p7h, q1.d, q1.c);
        const __half2 e4 = __hfma2(p7h, q2.b, q2.a);
        const __half2 e5 = __hfma2(p7h, q2.d, q2.c);
        const __half2 e6 = __hfma2(p7h, q3.b, q3.a);
        const __half2 e7 = __hfma2(p7h, q3.d, q3.c);
        // level B (p6): 4
        const __half2 f0 = __hfma2(p6h, e1, e0);
        const __half2 f1 = __hfma2(p6h, e3, e2);
        const __half2 f2 = __hfma2(p6h, e5, e4);
        const __half2 f3 = __hfma2(p6h, e7, e6);
        // level C (p5): 2
        const __half2 g0 = __hfma2(p5h, f1, f0);
        const __half2 g1 = __hfma2(p5h, f3, f2);
        // level D (p4): 1
        const __half2 inner = __hfma2(p4h, g1, g0);

        // lane combine = outer level over p3 (hi bit0)
        u[t] = fmaf(Pf[3], __high2float(inner), __low2float(inner));
    }

    // Remaining outer levels: t bit0<->p2, bit1<->p1, bit2<->p0  (7 FMA)
    const float v0 = fmaf(Pf[2], u[1], u[0]);
    const float v1 = fmaf(Pf[2], u[3], u[2]);
    const float v2 = fmaf(Pf[2], u[5], u[4]);
    const float v3 = fmaf(Pf[2], u[7], u[6]);
    const float m0 = fmaf(Pf[1], v1, v0);
    const float m1 = fmaf(Pf[1], v3, v2);
    const float res = fmaf(Pf[0], m1, m0);

    out[b * D + d] = res + lin_b[0];
}

extern "C" void kernel_launch(void* const* d_in, const int* in_sizes, int n_in,
                              void* d_out, int out_size) {
    const float* x     = (const float*)d_in[0];
    const float* k     = (const float*)d_in[1];
    const float* w     = (const float*)d_in[2];
    const float* q     = (const float*)d_in[3];
    // d_in[4] = mask (unused: fixed binary-expansion generation rule)
    const float* lin_w = (const float*)d_in[5];
    const float* lin_b = (const float*)d_in[6];
    float* out = (float*)d_out;

    // 128 threads = 4 warps; 1 batch row per warp -> 4 rows/block -> 2048 blocks
    dendrite_kernel<<<B / 4, 128>>>(x, k, w, q, lin_w, lin_b, out);
}